// round 1
// baseline (speedup 1.0000x reference)
#include <cuda_runtime.h>

// ---------------- problem constants ----------------
namespace {
constexpr int N_MOL  = 131072;
constexpr int E_MOL  = 524288;
constexpr int NG     = 4096;
constexpr int D_MOL  = 6;
constexpr int N_PROT = 100000;
constexpr int E_PROT = 1600000;
constexpr int D_PROT = 20;
constexpr int HD     = 64;
}

// ---------------- scratch (device globals; no allocation allowed) ----------------
__device__ __align__(256) float g_mA[N_MOL * HD];
__device__ __align__(256) float g_mB[N_MOL * HD];
__device__ __align__(256) float g_pA[N_PROT * HD];
__device__ __align__(256) float g_pB[N_PROT * HD];
__device__ float    g_dinv[N_MOL];      // degree, then deg^-1/2
__device__ float    g_hs[N_PROT];
__device__ float    g_hd[N_PROT];
__device__ float    g_ee[E_PROT];       // per-edge attention logit
__device__ unsigned g_menc[N_PROT];     // encoded segment max
__device__ float    g_m[N_PROT];        // decoded segment max
__device__ float    g_ss[N_PROT];       // softmax denominator
__device__ __align__(256) float g_molf[NG * HD];
__device__ float    g_cnt[NG];
__device__ float    g_protf[HD];

// ---------------- helpers ----------------
__device__ __forceinline__ float leaky02(float x) { return x > 0.f ? x : 0.2f * x; }

// order-preserving float <-> unsigned for atomicMax
__device__ __forceinline__ unsigned encf(float f) {
    unsigned u = __float_as_uint(f);
    return (u & 0x80000000u) ? ~u : (u | 0x80000000u);
}
__device__ __forceinline__ float decf(unsigned e) {
    unsigned u = (e & 0x80000000u) ? (e & 0x7fffffffu) : ~e;
    return __uint_as_float(u);
}

// vectorized fire-and-forget global atomic add (sm_90+)
__device__ __forceinline__ void red4(float* a, float x, float y, float z, float w) {
    asm volatile("red.global.add.v4.f32 [%0], {%1,%2,%3,%4};"
                 :: "l"(a), "f"(x), "f"(y), "f"(z), "f"(w) : "memory");
}

// ---------------- kernels ----------------

// zero pooling buffers; init degree = 1 (self loop)
__global__ void k_init() {
    int i = blockIdx.x * blockDim.x + threadIdx.x;
    if (i < NG * HD) g_molf[i] = 0.f;
    if (i < NG)      g_cnt[i]  = 0.f;
    if (i < HD)      g_protf[i] = 0.f;
    if (i < N_MOL)   g_dinv[i] = 1.f;
}

__global__ void k_deg(const int* __restrict__ dst) {
    int e = blockIdx.x * blockDim.x + threadIdx.x;
    if (e < E_MOL) atomicAdd(&g_dinv[dst[e]], 1.f);
}

__global__ void k_rsqrt() {
    int i = blockIdx.x * blockDim.x + threadIdx.x;
    if (i < N_MOL) g_dinv[i] = rsqrtf(g_dinv[i]);
}

// out[node][j] = sum_k (relu?)(in[node][k]) * W[k][j]
// W column j held in registers per lane; input row broadcast via shfl.
// block = 256 threads = 8 warps = 4 nodes per iteration (2 warps per node cover j 0..63)
template <int DIN, bool RELU_IN>
__global__ void k_matvec(const float* __restrict__ in, const float* __restrict__ W,
                         float* __restrict__ out, int n) {
    const int lane = threadIdx.x & 31;
    const int warp = threadIdx.x >> 5;
    const int j = ((warp & 1) << 5) | lane;
    float wreg[DIN];
#pragma unroll
    for (int k = 0; k < DIN; ++k) wreg[k] = __ldg(&W[k * HD + j]);
    const int step = gridDim.x * 4;
    for (int node = blockIdx.x * 4 + (warp >> 1); node < n; node += step) {
        const float* row = in + (long long)node * DIN;
        float r0 = 0.f, r1 = 0.f;
        if (DIN >= 32) {
            r0 = row[lane];
            if (DIN > 32 && lane + 32 < DIN) r1 = row[lane + 32];
        } else if (lane < DIN) {
            r0 = row[lane];
        }
        if (RELU_IN) { r0 = fmaxf(r0, 0.f); r1 = fmaxf(r1, 0.f); }
        float acc = 0.f;
#pragma unroll
        for (int k = 0; k < DIN; ++k) {
            float a = __shfl_sync(0xffffffffu, (k < 32) ? r0 : r1, k & 31);
            acc = fmaf(a, wreg[k], acc);
        }
        out[(long long)node * HD + j] = acc;
    }
}

// GCN: out = b + dinv[i]^2 * h[i]   (self-loop term)
__global__ void k_gcn_self(const float* __restrict__ h, float* __restrict__ out,
                           const float* __restrict__ b) {
    int idx = blockIdx.x * blockDim.x + threadIdx.x;
    if (idx >= N_MOL * 16) return;
    int i = idx >> 4, c = (idx & 15) << 2;
    float di = g_dinv[i];
    float coef = di * di;
    float4 h4 = *(const float4*)&h[i * HD + c];
    float4 b4 = *(const float4*)&b[c];
    float4 o;
    o.x = fmaf(coef, h4.x, b4.x);
    o.y = fmaf(coef, h4.y, b4.y);
    o.z = fmaf(coef, h4.z, b4.z);
    o.w = fmaf(coef, h4.w, b4.w);
    *(float4*)&out[i * HD + c] = o;
}

// GCN edge scatter: out[dst] += dinv[src]*dinv[dst] * h[src]
__global__ void k_gcn_edge(const int* __restrict__ src, const int* __restrict__ dst,
                           const float* __restrict__ h, float* __restrict__ out) {
    int idx = blockIdx.x * blockDim.x + threadIdx.x;
    if (idx >= E_MOL * 16) return;
    int e = idx >> 4, c = (idx & 15) << 2;
    int s = src[e], d = dst[e];
    float coef = g_dinv[s] * g_dinv[d];
    float4 h4 = *(const float4*)&h[s * HD + c];
    red4(&out[d * HD + c], h4.x * coef, h4.y * coef, h4.z * coef, h4.w * coef);
}

// GAT: per-node attention scalars hs = h.a_src, hd = h.a_dst; init segment max with self-loop
__global__ void k_att(const float* __restrict__ h, const float* __restrict__ asrc,
                      const float* __restrict__ adst) {
    int wid = (blockIdx.x * blockDim.x + threadIdx.x) >> 5;
    int lane = threadIdx.x & 31;
    if (wid >= N_PROT) return;
    float h0 = h[wid * HD + lane];
    float h1 = h[wid * HD + lane + 32];
    float s = h0 * __ldg(&asrc[lane]) + h1 * __ldg(&asrc[lane + 32]);
    float d = h0 * __ldg(&adst[lane]) + h1 * __ldg(&adst[lane + 32]);
#pragma unroll
    for (int o = 16; o; o >>= 1) {
        s += __shfl_xor_sync(0xffffffffu, s, o);
        d += __shfl_xor_sync(0xffffffffu, d, o);
    }
    if (lane == 0) {
        g_hs[wid] = s;
        g_hd[wid] = d;
        g_menc[wid] = encf(leaky02(s + d));  // self-loop initializes the max
    }
}

__global__ void k_edge_max(const int* __restrict__ src, const int* __restrict__ dst) {
    int e = blockIdx.x * blockDim.x + threadIdx.x;
    if (e >= E_PROT) return;
    int s = src[e], d = dst[e];
    float v = leaky02(g_hs[s] + g_hd[d]);
    g_ee[e] = v;
    atomicMax(&g_menc[d], encf(v));
}

// init unnormalized out with self-loop term; init denominator
__global__ void k_gat_self(const float* __restrict__ h, float* __restrict__ outun) {
    int idx = blockIdx.x * blockDim.x + threadIdx.x;
    if (idx >= N_PROT * 16) return;
    int i = idx >> 4, c = (idx & 15) << 2;
    float m = decf(g_menc[i]);
    float es = expf(leaky02(g_hs[i] + g_hd[i]) - m);
    float4 h4 = *(const float4*)&h[i * HD + c];
    float4 o;
    o.x = es * h4.x; o.y = es * h4.y; o.z = es * h4.z; o.w = es * h4.w;
    *(float4*)&outun[i * HD + c] = o;
    if (c == 0) { g_m[i] = m; g_ss[i] = es; }
}

__global__ void k_edge_sum(const int* __restrict__ src, const int* __restrict__ dst,
                           const float* __restrict__ h, float* __restrict__ outun) {
    int idx = blockIdx.x * blockDim.x + threadIdx.x;
    if (idx >= E_PROT * 16) return;
    int e = idx >> 4, c = (idx & 15) << 2;
    int s = src[e], d = dst[e];
    float ee = expf(g_ee[e] - g_m[d]);
    float4 h4 = *(const float4*)&h[s * HD + c];
    red4(&outun[d * HD + c], ee * h4.x, ee * h4.y, ee * h4.z, ee * h4.w);
    if (c == 0) atomicAdd(&g_ss[d], ee);
}

template <bool RELU>
__global__ void k_gat_final(float* __restrict__ o, const float* __restrict__ b) {
    int idx = blockIdx.x * blockDim.x + threadIdx.x;
    if (idx >= N_PROT * 16) return;
    int i = idx >> 4, c = (idx & 15) << 2;
    float inv = 1.f / g_ss[i];
    float4 v = *(float4*)&o[i * HD + c];
    float4 b4 = *(const float4*)&b[c];
    v.x = fmaf(v.x, inv, b4.x);
    v.y = fmaf(v.y, inv, b4.y);
    v.z = fmaf(v.z, inv, b4.z);
    v.w = fmaf(v.w, inv, b4.w);
    if (RELU) {
        v.x = fmaxf(v.x, 0.f); v.y = fmaxf(v.y, 0.f);
        v.z = fmaxf(v.z, 0.f); v.w = fmaxf(v.w, 0.f);
    }
    *(float4*)&o[i * HD + c] = v;
}

__global__ void k_mol_pool(const int* __restrict__ batch, const float* __restrict__ h) {
    int idx = blockIdx.x * blockDim.x + threadIdx.x;
    if (idx >= N_MOL * 16) return;
    int i = idx >> 4, c = (idx & 15) << 2;
    int g = batch[i];
    float4 v = *(const float4*)&h[i * HD + c];
    red4(&g_molf[g * HD + c], v.x, v.y, v.z, v.w);
    if (c == 0) atomicAdd(&g_cnt[g], 1.f);
}

__global__ void k_prot_pool(const float* __restrict__ h) {
    int j = threadIdx.x;           // 64
    float s = 0.f;
    for (int i = blockIdx.x; i < N_PROT; i += gridDim.x)
        s += h[(long long)i * HD + j];
    atomicAdd(&g_protf[j], s);
}

// classifier: one block (64 threads) per graph
__global__ void k_cls(const float* __restrict__ w1, const float* __restrict__ b1,
                      const float* __restrict__ w2, const float* __restrict__ b2,
                      float* __restrict__ out) {
    int g = blockIdx.x;
    int j = threadIdx.x;
    __shared__ float fused[2 * HD];
    __shared__ float red[2];
    float cnt = fmaxf(g_cnt[g], 1.f);
    fused[j] = g_molf[g * HD + j] / cnt;
    fused[HD + j] = g_protf[j] * (1.f / (float)N_PROT);
    __syncthreads();
    float z = __ldg(&b1[j]);
#pragma unroll
    for (int k = 0; k < 2 * HD; ++k)
        z = fmaf(fused[k], __ldg(&w1[k * HD + j]), z);
    z = fmaxf(z, 0.f);
    float t = z * __ldg(&w2[j]);
#pragma unroll
    for (int o = 16; o; o >>= 1) t += __shfl_xor_sync(0xffffffffu, t, o);
    if ((j & 31) == 0) red[j >> 5] = t;
    __syncthreads();
    if (j == 0)
        out[g] = 1.f / (1.f + expf(-(red[0] + red[1] + __ldg(&b2[0]))));
}

// ---------------- launch ----------------
extern "C" void kernel_launch(void* const* d_in, const int* in_sizes, int n_in,
                              void* d_out, int out_size) {
    const float* mol_x  = (const float*)d_in[0];
    const int*   mei    = (const int*)  d_in[1];
    const int*   mbatch = (const int*)  d_in[2];
    const float* prot_x = (const float*)d_in[3];
    const int*   pei    = (const int*)  d_in[4];
    const float* gw1 = (const float*)d_in[5];
    const float* gb1 = (const float*)d_in[6];
    const float* gw2 = (const float*)d_in[7];
    const float* gb2 = (const float*)d_in[8];
    const float* aw1 = (const float*)d_in[9];
    const float* as1 = (const float*)d_in[10];
    const float* ad1 = (const float*)d_in[11];
    const float* ab1 = (const float*)d_in[12];
    const float* aw2 = (const float*)d_in[13];
    const float* as2 = (const float*)d_in[14];
    const float* ad2 = (const float*)d_in[15];
    const float* ab2 = (const float*)d_in[16];
    const float* cw1 = (const float*)d_in[17];
    const float* cb1 = (const float*)d_in[18];
    const float* cw2 = (const float*)d_in[19];
    const float* cb2 = (const float*)d_in[20];
    float* out = (float*)d_out;

    float *mA, *mB, *pA, *pB;
    cudaGetSymbolAddress((void**)&mA, g_mA);
    cudaGetSymbolAddress((void**)&mB, g_mB);
    cudaGetSymbolAddress((void**)&pA, g_pA);
    cudaGetSymbolAddress((void**)&pB, g_pB);

    const int* msrc = mei;
    const int* mdst = mei + E_MOL;
    const int* psrc = pei;
    const int* pdst = pei + E_PROT;

    const int T = 256;
    k_init<<<(NG * HD + T - 1) / T, T>>>();

    // ---- molecular branch (GCN x2) ----
    k_deg<<<(E_MOL + T - 1) / T, T>>>(mdst);
    k_rsqrt<<<(N_MOL + T - 1) / T, T>>>();

    k_matvec<D_MOL, false><<<2048, T>>>(mol_x, gw1, mA, N_MOL);
    k_gcn_self<<<(N_MOL * 16 + T - 1) / T, T>>>(mA, mB, gb1);
    k_gcn_edge<<<(E_MOL * 16 + T - 1) / T, T>>>(msrc, mdst, mA, mB);

    k_matvec<HD, true><<<2048, T>>>(mB, gw2, mA, N_MOL);   // relu fused on input
    k_gcn_self<<<(N_MOL * 16 + T - 1) / T, T>>>(mA, mB, gb2);
    k_gcn_edge<<<(E_MOL * 16 + T - 1) / T, T>>>(msrc, mdst, mA, mB);

    k_mol_pool<<<(N_MOL * 16 + T - 1) / T, T>>>(mbatch, mB);

    // ---- protein branch (GAT x2) ----
    k_matvec<D_PROT, false><<<2048, T>>>(prot_x, aw1, pA, N_PROT);
    k_att<<<(N_PROT * 32 + T - 1) / T, T>>>(pA, as1, ad1);
    k_edge_max<<<(E_PROT + T - 1) / T, T>>>(psrc, pdst);
    k_gat_self<<<(N_PROT * 16 + T - 1) / T, T>>>(pA, pB);
    k_edge_sum<<<(E_PROT * 16 + T - 1) / T, T>>>(psrc, pdst, pA, pB);
    k_gat_final<true><<<(N_PROT * 16 + T - 1) / T, T>>>(pB, ab1);

    k_matvec<HD, false><<<2048, T>>>(pB, aw2, pA, N_PROT);
    k_att<<<(N_PROT * 32 + T - 1) / T, T>>>(pA, as2, ad2);
    k_edge_max<<<(E_PROT + T - 1) / T, T>>>(psrc, pdst);
    k_gat_self<<<(N_PROT * 16 + T - 1) / T, T>>>(pA, pB);
    k_edge_sum<<<(E_PROT * 16 + T - 1) / T, T>>>(psrc, pdst, pA, pB);
    k_gat_final<false><<<(N_PROT * 16 + T - 1) / T, T>>>(pB, ab2);

    k_prot_pool<<<512, 64>>>(pB);

    // ---- classifier ----
    k_cls<<<NG, HD>>>(cw1, cb1, cw2, cb2, out);
}

// round 2
// speedup vs baseline: 1.2269x; 1.2269x over previous
#include <cuda_runtime.h>

// ---------------- problem constants ----------------
namespace {
constexpr int N_MOL  = 131072;
constexpr int E_MOL  = 524288;
constexpr int NG     = 4096;
constexpr int D_MOL  = 6;
constexpr int N_PROT = 100000;
constexpr int E_PROT = 1600000;
constexpr int D_PROT = 20;
constexpr int HD     = 64;
}

// ---------------- scratch (device globals; no allocation allowed) ----------------
__device__ __align__(256) float g_mA[N_MOL * HD];
__device__ __align__(256) float g_mB[N_MOL * HD];
__device__ __align__(256) float g_pA[N_PROT * HD];
__device__ __align__(256) float g_pB[N_PROT * HD];
// CSR-by-dst for both graphs
__device__ int g_mcnt[N_MOL];
__device__ int g_moff[N_MOL + 1];
__device__ int g_mcur[N_MOL];
__device__ int g_msrc[E_MOL];
__device__ int g_pcnt[N_PROT];
__device__ int g_poff[N_PROT + 1];
__device__ int g_pcur[N_PROT];
__device__ int g_psrc[E_PROT];
__device__ int g_part[256];          // scan partials
__device__ float g_dinv[N_MOL];
__device__ float g_hs[N_PROT];
__device__ float g_hd[N_PROT];
__device__ __align__(256) float g_molf[NG * HD];
__device__ float g_gcnt[NG];
__device__ float g_protf[HD];

// ---------------- helpers ----------------
__device__ __forceinline__ float leaky02(float x) { return x > 0.f ? x : 0.2f * x; }

__device__ __forceinline__ void red4(float* a, float x, float y, float z, float w) {
    asm volatile("red.global.add.v4.f32 [%0], {%1,%2,%3,%4};"
                 :: "l"(a), "f"(x), "f"(y), "f"(z), "f"(w) : "memory");
}

// ---------------- setup kernels ----------------
__global__ void k_init() {
    int i = blockIdx.x * blockDim.x + threadIdx.x;   // covers 262144
    if (i < NG * HD) g_molf[i] = 0.f;
    if (i < NG)      g_gcnt[i] = 0.f;
    if (i < HD)      g_protf[i] = 0.f;
    if (i < N_MOL)   g_mcnt[i] = 0;
    if (i < N_PROT)  g_pcnt[i] = 0;
}

__global__ void k_hist(const int* __restrict__ dst, int* __restrict__ cnt, int E) {
    int e = blockIdx.x * blockDim.x + threadIdx.x;
    if (e < E) atomicAdd(&cnt[dst[e]], 1);
}

// block scan: 256 threads x 4 elems = 1024 elems/block; writes exclusive prefix
// (block-local) to off and the block total to part.
__global__ void k_scan1(const int* __restrict__ cnt, int* __restrict__ off,
                        int* __restrict__ part, int n) {
    __shared__ int wsum[8];
    int t = threadIdx.x;
    int base = blockIdx.x * 1024 + t * 4;
    int v0 = 0, v1 = 0, v2 = 0, v3 = 0;
    if (base + 3 < n) {
        int4 v = *(const int4*)&cnt[base];
        v0 = v.x; v1 = v.y; v2 = v.z; v3 = v.w;
    } else {
        if (base + 0 < n) v0 = cnt[base + 0];
        if (base + 1 < n) v1 = cnt[base + 1];
        if (base + 2 < n) v2 = cnt[base + 2];
        if (base + 3 < n) v3 = cnt[base + 3];
    }
    int s = v0 + v1 + v2 + v3;
    int lane = t & 31, w = t >> 5;
    int inc = s;
#pragma unroll
    for (int o = 1; o < 32; o <<= 1) {
        int x = __shfl_up_sync(0xffffffffu, inc, o);
        if (lane >= o) inc += x;
    }
    if (lane == 31) wsum[w] = inc;
    __syncthreads();
    int wbase = 0;
    for (int i = 0; i < w; i++) wbase += wsum[i];
    int ex = wbase + inc - s;
    if (base + 0 < n) off[base + 0] = ex;
    if (base + 1 < n) off[base + 1] = ex + v0;
    if (base + 2 < n) off[base + 2] = ex + v0 + v1;
    if (base + 3 < n) off[base + 3] = ex + v0 + v1 + v2;
    if (t == 255) part[blockIdx.x] = wbase + inc;
}

// scan of block totals (nb <= 128), in-place exclusive
__global__ void k_scan_tot(int* __restrict__ part, int nb) {
    __shared__ int ws[4];
    int t = threadIdx.x;                 // 128 threads
    int v = (t < nb) ? part[t] : 0;
    int lane = t & 31, w = t >> 5;
    int inc = v;
#pragma unroll
    for (int o = 1; o < 32; o <<= 1) {
        int x = __shfl_up_sync(0xffffffffu, inc, o);
        if (lane >= o) inc += x;
    }
    if (lane == 31) ws[w] = inc;
    __syncthreads();
    int wbase = 0;
    for (int i = 0; i < w; i++) wbase += ws[i];
    if (t < nb) part[t] = wbase + inc - v;
}

__global__ void k_scan_add(int* __restrict__ off, const int* __restrict__ part,
                           int* __restrict__ cur, int n, int e_total) {
    int i = blockIdx.x * blockDim.x + threadIdx.x;
    if (i < n) {
        int o = off[i] + part[i >> 10];
        off[i] = o;
        cur[i] = o;
    }
    if (i == 0) off[n] = e_total;
}

__global__ void k_fill(const int* __restrict__ src, const int* __restrict__ dst,
                       int* __restrict__ cur, int* __restrict__ srcs, int E) {
    int e = blockIdx.x * blockDim.x + threadIdx.x;
    if (e < E) {
        int slot = atomicAdd(&cur[dst[e]], 1);
        srcs[slot] = src[e];
    }
}

__global__ void k_dinv() {
    int i = blockIdx.x * blockDim.x + threadIdx.x;
    if (i < N_MOL) g_dinv[i] = rsqrtf((float)(g_mcnt[i] + 1));
}

// ---------------- dense matvec: out[node][j] = sum_k (relu?)in[node][k] * W[k][j] ----------------
template <int DIN, bool RELU_IN>
__global__ void k_matvec(const float* __restrict__ in, const float* __restrict__ W,
                         float* __restrict__ out, int n) {
    const int lane = threadIdx.x & 31;
    const int warp = threadIdx.x >> 5;
    const int j = ((warp & 1) << 5) | lane;
    float wreg[DIN];
#pragma unroll
    for (int k = 0; k < DIN; ++k) wreg[k] = __ldg(&W[k * HD + j]);
    const int step = gridDim.x * 4;
    for (int node = blockIdx.x * 4 + (warp >> 1); node < n; node += step) {
        const float* row = in + (size_t)node * DIN;
        float r0 = 0.f, r1 = 0.f;
        if (DIN >= 32) {
            r0 = row[lane];
            if (DIN > 32 && lane + 32 < DIN) r1 = row[lane + 32];
        } else if (lane < DIN) {
            r0 = row[lane];
        }
        if (RELU_IN) { r0 = fmaxf(r0, 0.f); r1 = fmaxf(r1, 0.f); }
        float acc = 0.f;
#pragma unroll
        for (int k = 0; k < DIN; ++k) {
            float a = __shfl_sync(0xffffffffu, (k < 32) ? r0 : r1, k & 31);
            acc = fmaf(a, wreg[k], acc);
        }
        out[(size_t)node * HD + j] = acc;
    }
}

// ---------------- GCN accumulate (warp per dst node) ----------------
// out[d] = b + dinv[d]^2 h[d] + sum_{e: dst=d} dinv[src]dinv[d] h[src]
// POOL: instead of writing out, red4 into g_molf[batch[d]] (+count)
template <bool POOL>
__global__ void k_gcn_acc(const float* __restrict__ h, float* __restrict__ out,
                          const float* __restrict__ bias, const int* __restrict__ batch) {
    int wid = (blockIdx.x * blockDim.x + threadIdx.x) >> 5;
    if (wid >= N_MOL) return;
    int lane = threadIdx.x & 31;
    int half = lane >> 4;
    int c4 = (lane & 15) << 2;
    int beg = g_moff[wid], end = g_moff[wid + 1];
    float dd = g_dinv[wid];
    float4 acc = {0.f, 0.f, 0.f, 0.f};
    if (half == 0) {
        float cs = dd * dd;
        float4 hv = *(const float4*)&h[(size_t)wid * HD + c4];
        acc.x = cs * hv.x; acc.y = cs * hv.y; acc.z = cs * hv.z; acc.w = cs * hv.w;
    }
    for (int base = beg; base < end; base += 32) {
        int nn = min(32, end - base);
        int s = (lane < nn) ? g_msrc[base + lane] : 0;
        float cf = (lane < nn) ? g_dinv[s] * dd : 0.f;
#pragma unroll 4
        for (int k = 0; k < nn; k += 2) {
            int idx = k + half;
            int sk = __shfl_sync(0xffffffffu, s, idx);
            float ck = __shfl_sync(0xffffffffu, cf, idx);
            if (idx < nn) {
                float4 hv = *(const float4*)&h[(size_t)sk * HD + c4];
                acc.x = fmaf(ck, hv.x, acc.x);
                acc.y = fmaf(ck, hv.y, acc.y);
                acc.z = fmaf(ck, hv.z, acc.z);
                acc.w = fmaf(ck, hv.w, acc.w);
            }
        }
    }
    acc.x += __shfl_xor_sync(0xffffffffu, acc.x, 16);
    acc.y += __shfl_xor_sync(0xffffffffu, acc.y, 16);
    acc.z += __shfl_xor_sync(0xffffffffu, acc.z, 16);
    acc.w += __shfl_xor_sync(0xffffffffu, acc.w, 16);
    if (lane < 16) {
        float4 b4 = *(const float4*)&bias[c4];
        acc.x += b4.x; acc.y += b4.y; acc.z += b4.z; acc.w += b4.w;
        if (POOL) {
            int g = batch[wid];
            red4(&g_molf[(size_t)g * HD + c4], acc.x, acc.y, acc.z, acc.w);
            if (lane == 0) atomicAdd(&g_gcnt[g], 1.f);
        } else {
            *(float4*)&out[(size_t)wid * HD + c4] = acc;
        }
    }
}

// ---------------- GAT per-node attention scalars ----------------
__global__ void k_att(const float* __restrict__ h, const float* __restrict__ asrc,
                      const float* __restrict__ adst) {
    int wid = (blockIdx.x * blockDim.x + threadIdx.x) >> 5;
    int lane = threadIdx.x & 31;
    if (wid >= N_PROT) return;
    float h0 = h[(size_t)wid * HD + lane];
    float h1 = h[(size_t)wid * HD + lane + 32];
    float s = h0 * __ldg(&asrc[lane]) + h1 * __ldg(&asrc[lane + 32]);
    float d = h0 * __ldg(&adst[lane]) + h1 * __ldg(&adst[lane + 32]);
#pragma unroll
    for (int o = 16; o; o >>= 1) {
        s += __shfl_xor_sync(0xffffffffu, s, o);
        d += __shfl_xor_sync(0xffffffffu, d, o);
    }
    if (lane == 0) { g_hs[wid] = s; g_hd[wid] = d; }
}

// ---------------- GAT accumulate (warp per dst node, softmax warp-local) ----------------
template <bool RELU_OUT>
__global__ void k_gat_acc(const float* __restrict__ h, float* __restrict__ out,
                          const float* __restrict__ bias) {
    int wid = (blockIdx.x * blockDim.x + threadIdx.x) >> 5;
    if (wid >= N_PROT) return;
    int lane = threadIdx.x & 31;
    int half = lane >> 4;
    int c4 = (lane & 15) << 2;
    int beg = g_poff[wid], end = g_poff[wid + 1];
    float hdv = g_hd[wid];
    float eself = leaky02(g_hs[wid] + hdv);
    // phase 1: segment max (self-loop included)
    float m = eself;
    for (int i = beg + lane; i < end; i += 32)
        m = fmaxf(m, leaky02(g_hs[g_psrc[i]] + hdv));
#pragma unroll
    for (int o = 16; o; o >>= 1)
        m = fmaxf(m, __shfl_xor_sync(0xffffffffu, m, o));
    // phase 2: weighted accumulation
    float wself = __expf(eself - m);
    float ssum = (lane == 0) ? wself : 0.f;
    float4 acc = {0.f, 0.f, 0.f, 0.f};
    if (half == 0) {
        float4 hv = *(const float4*)&h[(size_t)wid * HD + c4];
        acc.x = wself * hv.x; acc.y = wself * hv.y;
        acc.z = wself * hv.z; acc.w = wself * hv.w;
    }
    for (int base = beg; base < end; base += 32) {
        int nn = min(32, end - base);
        int s = (lane < nn) ? g_psrc[base + lane] : 0;
        float wgt = (lane < nn) ? __expf(leaky02(g_hs[s] + hdv) - m) : 0.f;
        ssum += wgt;
#pragma unroll 4
        for (int k = 0; k < nn; k += 2) {
            int idx = k + half;
            int sk = __shfl_sync(0xffffffffu, s, idx);
            float wk = __shfl_sync(0xffffffffu, wgt, idx);
            if (idx < nn) {
                float4 hv = *(const float4*)&h[(size_t)sk * HD + c4];
                acc.x = fmaf(wk, hv.x, acc.x);
                acc.y = fmaf(wk, hv.y, acc.y);
                acc.z = fmaf(wk, hv.z, acc.z);
                acc.w = fmaf(wk, hv.w, acc.w);
            }
        }
    }
    acc.x += __shfl_xor_sync(0xffffffffu, acc.x, 16);
    acc.y += __shfl_xor_sync(0xffffffffu, acc.y, 16);
    acc.z += __shfl_xor_sync(0xffffffffu, acc.z, 16);
    acc.w += __shfl_xor_sync(0xffffffffu, acc.w, 16);
#pragma unroll
    for (int o = 16; o; o >>= 1)
        ssum += __shfl_xor_sync(0xffffffffu, ssum, o);
    if (lane < 16) {
        float inv = 1.f / ssum;
        float4 b4 = *(const float4*)&bias[c4];
        float4 v;
        v.x = fmaf(acc.x, inv, b4.x);
        v.y = fmaf(acc.y, inv, b4.y);
        v.z = fmaf(acc.z, inv, b4.z);
        v.w = fmaf(acc.w, inv, b4.w);
        if (RELU_OUT) {
            v.x = fmaxf(v.x, 0.f); v.y = fmaxf(v.y, 0.f);
            v.z = fmaxf(v.z, 0.f); v.w = fmaxf(v.w, 0.f);
        }
        *(float4*)&out[(size_t)wid * HD + c4] = v;
    }
}

// ---------------- pooling + classifier ----------------
__global__ void k_prot_pool(const float* __restrict__ h) {
    int j = threadIdx.x;  // 64
    float s = 0.f;
    for (int i = blockIdx.x; i < N_PROT; i += gridDim.x)
        s += h[(size_t)i * HD + j];
    atomicAdd(&g_protf[j], s);
}

__global__ void k_cls(const float* __restrict__ w1, const float* __restrict__ b1,
                      const float* __restrict__ w2, const float* __restrict__ b2,
                      float* __restrict__ out) {
    int g = blockIdx.x;
    int j = threadIdx.x;
    __shared__ float fused[2 * HD];
    __shared__ float red[2];
    float cnt = fmaxf(g_gcnt[g], 1.f);
    fused[j] = g_molf[g * HD + j] / cnt;
    fused[HD + j] = g_protf[j] * (1.f / (float)N_PROT);
    __syncthreads();
    float z = __ldg(&b1[j]);
#pragma unroll
    for (int k = 0; k < 2 * HD; ++k)
        z = fmaf(fused[k], __ldg(&w1[k * HD + j]), z);
    z = fmaxf(z, 0.f);
    float t = z * __ldg(&w2[j]);
#pragma unroll
    for (int o = 16; o; o >>= 1) t += __shfl_xor_sync(0xffffffffu, t, o);
    if ((j & 31) == 0) red[j >> 5] = t;
    __syncthreads();
    if (j == 0)
        out[g] = 1.f / (1.f + expf(-(red[0] + red[1] + __ldg(&b2[0]))));
}

// ---------------- launch ----------------
extern "C" void kernel_launch(void* const* d_in, const int* in_sizes, int n_in,
                              void* d_out, int out_size) {
    const float* mol_x  = (const float*)d_in[0];
    const int*   mei    = (const int*)  d_in[1];
    const int*   mbatch = (const int*)  d_in[2];
    const float* prot_x = (const float*)d_in[3];
    const int*   pei    = (const int*)  d_in[4];
    const float* gw1 = (const float*)d_in[5];
    const float* gb1 = (const float*)d_in[6];
    const float* gw2 = (const float*)d_in[7];
    const float* gb2 = (const float*)d_in[8];
    const float* aw1 = (const float*)d_in[9];
    const float* as1 = (const float*)d_in[10];
    const float* ad1 = (const float*)d_in[11];
    const float* ab1 = (const float*)d_in[12];
    const float* aw2 = (const float*)d_in[13];
    const float* as2 = (const float*)d_in[14];
    const float* ad2 = (const float*)d_in[15];
    const float* ab2 = (const float*)d_in[16];
    const float* cw1 = (const float*)d_in[17];
    const float* cb1 = (const float*)d_in[18];
    const float* cw2 = (const float*)d_in[19];
    const float* cb2 = (const float*)d_in[20];
    float* out = (float*)d_out;

    float *mA, *mB, *pA, *pB;
    cudaGetSymbolAddress((void**)&mA, g_mA);
    cudaGetSymbolAddress((void**)&mB, g_mB);
    cudaGetSymbolAddress((void**)&pA, g_pA);
    cudaGetSymbolAddress((void**)&pB, g_pB);
    int *mcnt, *moff, *mcur, *msrcs, *pcnt, *poff, *pcur, *psrcs, *part;
    cudaGetSymbolAddress((void**)&mcnt, g_mcnt);
    cudaGetSymbolAddress((void**)&moff, g_moff);
    cudaGetSymbolAddress((void**)&mcur, g_mcur);
    cudaGetSymbolAddress((void**)&msrcs, g_msrc);
    cudaGetSymbolAddress((void**)&pcnt, g_pcnt);
    cudaGetSymbolAddress((void**)&poff, g_poff);
    cudaGetSymbolAddress((void**)&pcur, g_pcur);
    cudaGetSymbolAddress((void**)&psrcs, g_psrc);
    cudaGetSymbolAddress((void**)&part, g_part);

    const int* msrc = mei;
    const int* mdst = mei + E_MOL;
    const int* psrc = pei;
    const int* pdst = pei + E_PROT;

    const int T = 256;
    k_init<<<(NG * HD + T - 1) / T, T>>>();

    // ---- build CSR (mol) ----
    k_hist<<<(E_MOL + T - 1) / T, T>>>(mdst, mcnt, E_MOL);
    k_scan1<<<(N_MOL + 1023) / 1024, 256>>>(mcnt, moff, part, N_MOL);
    k_scan_tot<<<1, 128>>>(part, (N_MOL + 1023) / 1024);
    k_scan_add<<<(N_MOL + T - 1) / T, T>>>(moff, part, mcur, N_MOL, E_MOL);
    k_fill<<<(E_MOL + T - 1) / T, T>>>(msrc, mdst, mcur, msrcs, E_MOL);
    k_dinv<<<(N_MOL + T - 1) / T, T>>>();

    // ---- molecular branch (GCN x2) ----
    k_matvec<D_MOL, false><<<2048, T>>>(mol_x, gw1, mA, N_MOL);
    k_gcn_acc<false><<<(N_MOL + 7) / 8, T>>>(mA, mB, gb1, mbatch);
    k_matvec<HD, true><<<2048, T>>>(mB, gw2, mA, N_MOL);
    k_gcn_acc<true><<<(N_MOL + 7) / 8, T>>>(mA, mB, gb2, mbatch);   // fused pool

    // ---- build CSR (prot) ----
    k_hist<<<(E_PROT + T - 1) / T, T>>>(pdst, pcnt, E_PROT);
    k_scan1<<<(N_PROT + 1023) / 1024, 256>>>(pcnt, poff, part, N_PROT);
    k_scan_tot<<<1, 128>>>(part, (N_PROT + 1023) / 1024);
    k_scan_add<<<(N_PROT + T - 1) / T, T>>>(poff, part, pcur, N_PROT, E_PROT);
    k_fill<<<(E_PROT + T - 1) / T, T>>>(psrc, pdst, pcur, psrcs, E_PROT);

    // ---- protein branch (GAT x2) ----
    k_matvec<D_PROT, false><<<2048, T>>>(prot_x, aw1, pA, N_PROT);
    k_att<<<(N_PROT * 32 + T - 1) / T, T>>>(pA, as1, ad1);
    k_gat_acc<true><<<(N_PROT + 7) / 8, T>>>(pA, pB, ab1);

    k_matvec<HD, false><<<2048, T>>>(pB, aw2, pA, N_PROT);
    k_att<<<(N_PROT * 32 + T - 1) / T, T>>>(pA, as2, ad2);
    k_gat_acc<false><<<(N_PROT + 7) / 8, T>>>(pA, pB, ab2);

    k_prot_pool<<<512, 64>>>(pB);

    // ---- classifier ----
    k_cls<<<NG, HD>>>(cw1, cb1, cw2, cb2, out);
}